// round 3
// baseline (speedup 1.0000x reference)
#include <cuda_runtime.h>
#include <cuda_fp16.h>

#define HH 2048
#define WW 2048
#define HWN (HH*WW)
#define W2 (WW/2)            // float2 columns per row = 1024
#define HW2 (HWN/2)          // float2 per plane
#define NCTA 296
#define NTHR 1024
#define MAXR 7
#define SUB 8
#define MAXPAIRS (MAXR*W2)   // 7168 pixel-pairs per CTA max

// dyn smem: s_im uint[7168]=28672B, s_rm uint[7168]=28672B, lut 1024B, cdf 1024B, hist 8192B
#define SMEM_BYTES (MAXPAIRS*4*2 + 1024 + 1024 + 256*SUB*4)

__device__ double g_sums[4];      // 0:recon 1:r_smooth(x255) 2:ismooth 3:eq
__device__ unsigned int g_hist[256];
__device__ int g_minbits;
__device__ int g_maxbits;
__device__ unsigned int g_bar;

__global__ void k_zero() {
    int t = threadIdx.x;
    if (t < 256) g_hist[t] = 0u;
    if (t < 4) g_sums[t] = 0.0;
    if (t == 0) { g_minbits = 0x7F800000; g_maxbits = 0; g_bar = 0u; }
}

// PIL 'L' grayscale on 8-bit quantized input; returns INTEGER gray 0..255 as float.
__device__ __forceinline__ float grayc(float r, float g, float b) {
    float q0 = floorf(__saturatef(r) * 255.0f);
    float q1 = floorf(__saturatef(g) * 255.0f);
    float q2 = floorf(__saturatef(b) * 255.0f);
    return floorf((q0 * 19595.0f + q1 * 38470.0f + q2 * 7471.0f + 32768.0f) * (1.0f / 65536.0f));
}

__device__ __forceinline__ unsigned packh2(float a, float b) {
    __half2 h = __floats2half2_rn(a, b);
    return *reinterpret_cast<unsigned*>(&h);
}
__device__ __forceinline__ float2 unpackh2(unsigned u) {
    __half2 h = *reinterpret_cast<__half2*>(&u);
    return __half22float2(h);
}

// Software grid barrier. Residency guaranteed: launch_bounds(1024,2) caps regs
// at 32 (2*1024*32 = 64K RF), smem 67.6KB*2 < 228KB -> exactly 2 CTAs/SM,
// 2*148 = 296 = NCTA (GB300 has 152 SMs: headroom).
__device__ __forceinline__ void gridbar(unsigned target) {
    __syncthreads();
    if (threadIdx.x == 0) {
        __threadfence();
        atomicAdd(&g_bar, 1u);
        while (*(volatile unsigned*)&g_bar < target) { }
    }
    __syncthreads();
    __threadfence();
}

__device__ __forceinline__ float interp1(float x, float gmin, float scale, const float* cdf) {
    float u = fmaxf((x - gmin) * scale, 0.0f);   // clamp: fp16-rounded x may dip below gmin
    int k = (int)u;
    if (k >= 255) return cdf[255];
    float f = u - (float)k;
    return cdf[k] + (cdf[k + 1] - cdf[k]) * f;
}

__global__ __launch_bounds__(NTHR, 2) void kmain(const float2* __restrict__ in,
                                                 const float2* __restrict__ Rp,
                                                 const float2* __restrict__ Lp,
                                                 float* __restrict__ out) {
    extern __shared__ char sm[];
    unsigned* s_im  = (unsigned*)sm;                       // fp16x2 im_max
    unsigned* s_rm  = (unsigned*)(sm + MAXPAIRS * 4);      // fp16x2 r_max
    float*    s_lut = (float*)(sm + MAXPAIRS * 8);
    float*    s_cdf = s_lut + 256;
    unsigned* s_h   = (unsigned*)(s_cdf + 256);
    __shared__ double redd[3][32];
    __shared__ float  redf[2][32];

    const int tid = threadIdx.x;
    const int cta = blockIdx.x;

    // slab: CTAs 0..271 -> 7 rows, 272..295 -> 6 rows (272*7 + 24*6 = 2048)
    int nr, r0;
    if (cta < 272) { nr = 7; r0 = cta * 7; }
    else           { nr = 6; r0 = 1904 + (cta - 272) * 6; }

    for (int i = tid; i < 256; i += NTHR)
        s_lut[i] = __expf((float)i * (-10.0f / 255.0f));
    __syncthreads();

    // ---------------- Phase 1: fused per-pixel pass ----------------
    float gPx, gPy, lPx, lPy;
    if (r0 == 0) {
        gPx = gPy = lPx = lPy = 0.0f;
    } else {
        int idx = (r0 - 1) * W2 + tid;
        float2 b0 = Rp[idx], b1 = Rp[idx + HW2], b2 = Rp[idx + 2 * HW2];
        float2 lv = Lp[idx];
        gPx = grayc(b0.x, b1.x, b2.x);
        gPy = grayc(b0.y, b1.y, b2.y);
        lPx = lv.x; lPy = lv.y;
    }

    float sRec = 0.f, sRs = 0.f, sIs = 0.f;
    float vmin = 3.0f, vmax = -1.0f;

    #pragma unroll 1
    for (int rr = 0; rr < nr; rr++) {
        int idx = (r0 + rr) * W2 + tid;
        float2 a0 = in[idx], a1 = in[idx + HW2], a2 = in[idx + 2 * HW2];
        float2 b0 = Rp[idx], b1 = Rp[idx + HW2], b2 = Rp[idx + 2 * HW2];
        float2 lv = Lp[idx];

        float rec =
            fabsf(b0.x * lv.x - a0.x) + fabsf(b0.y * lv.y - a0.y) +
            fabsf(b1.x * lv.x - a1.x) + fabsf(b1.y * lv.y - a1.y) +
            fabsf(b2.x * lv.x - a2.x) + fabsf(b2.y * lv.y - a2.y);

        float imx = fmaxf(a0.x, fmaxf(a1.x, a2.x));
        float imy = fmaxf(a0.y, fmaxf(a1.y, a2.y));
        float rmx = fmaxf(b0.x, fmaxf(b1.x, b2.x));
        float rmy = fmaxf(b0.y, fmaxf(b1.y, b2.y));

        int li = rr * W2 + tid;
        s_im[li] = packh2(imx, imy);
        s_rm[li] = packh2(rmx, rmy);

        vmin = fminf(vmin, fminf(imx, imy));
        vmax = fmaxf(vmax, fmaxf(imx, imy));

        float gx = grayc(b0.x, b1.x, b2.x);
        float gy = grayc(b0.y, b1.y, b2.y);

        float rs, is;
        {
            float dg = fabsf(gx - gPx);
            rs = dg + 2.0f * gx;
            is = fabsf(lv.x - lPx) * s_lut[(int)dg] + 2.0f * fabsf(lv.x) * s_lut[(int)gx];
        }
        {
            float dg = fabsf(gy - gPy);
            rs += dg + 2.0f * gy;
            is += fabsf(lv.y - lPy) * s_lut[(int)dg] + 2.0f * fabsf(lv.y) * s_lut[(int)gy];
        }
        sRec += rec;
        sRs  += rs;
        sIs  += is;
        gPx = gx; gPy = gy; lPx = lv.x; lPy = lv.y;
    }

    if (r0 + nr == HH) {   // bottom padded edge
        sRs += gPx + gPy;
        sIs += fabsf(lPx) * s_lut[(int)gPx] + fabsf(lPy) * s_lut[(int)gPy];
    }

    // block reduce (32 warps), promote to double
    double dRec = (double)sRec, dRs = (double)sRs, dIs = (double)sIs;
    const unsigned m = 0xffffffffu;
    for (int o = 16; o; o >>= 1) {
        dRec += __shfl_down_sync(m, dRec, o);
        dRs  += __shfl_down_sync(m, dRs,  o);
        dIs  += __shfl_down_sync(m, dIs,  o);
        vmin = fminf(vmin, __shfl_down_sync(m, vmin, o));
        vmax = fmaxf(vmax, __shfl_down_sync(m, vmax, o));
    }
    int lane = tid & 31, wid = tid >> 5;
    if (lane == 0) {
        redd[0][wid] = dRec; redd[1][wid] = dRs; redd[2][wid] = dIs;
        redf[0][wid] = vmin; redf[1][wid] = vmax;
    }
    __syncthreads();
    if (wid == 0) {
        dRec = redd[0][lane];
        dRs  = redd[1][lane];
        dIs  = redd[2][lane];
        vmin = redf[0][lane];
        vmax = redf[1][lane];
        for (int o = 16; o; o >>= 1) {
            dRec += __shfl_down_sync(m, dRec, o);
            dRs  += __shfl_down_sync(m, dRs,  o);
            dIs  += __shfl_down_sync(m, dIs,  o);
            vmin = fminf(vmin, __shfl_down_sync(m, vmin, o));
            vmax = fmaxf(vmax, __shfl_down_sync(m, vmax, o));
        }
        if (lane == 0) {
            atomicAdd(&g_sums[0], dRec);
            atomicAdd(&g_sums[1], dRs);
            atomicAdd(&g_sums[2], dIs);
            atomicMin(&g_minbits, __float_as_int(vmin));   // all values >= 0
            atomicMax(&g_maxbits, __float_as_int(vmax));
        }
    }

    gridbar(NCTA);

    // ---------------- Phase 2: histogram from smem ----------------
    const float gmin = __int_as_float(__ldcg(&g_minbits));
    const float gmax = __int_as_float(__ldcg(&g_maxbits));
    const float scale = 256.0f / (gmax - gmin);

    for (int i = tid; i < 256 * SUB; i += NTHR) s_h[i] = 0u;
    __syncthreads();
    const unsigned sub = tid & (SUB - 1);
    const int npairs = nr * W2;
    for (int i = tid; i < npairs; i += NTHR) {
        float2 v = unpackh2(s_im[i]);
        int k0 = min(255, (int)fmaxf((v.x - gmin) * scale, 0.0f));
        int k1 = min(255, (int)fmaxf((v.y - gmin) * scale, 0.0f));
        atomicAdd(&s_h[k0 * SUB + sub], 1u);
        atomicAdd(&s_h[k1 * SUB + sub], 1u);
    }
    __syncthreads();
    if (tid < 256) {
        unsigned s = 0;
        #pragma unroll
        for (int j = 0; j < SUB; j++) s += s_h[tid * SUB + j];
        if (s) atomicAdd(&g_hist[tid], s);
    }

    gridbar(2 * NCTA);

    // ---------------- Phase 3: cdf scan + interp + eq-sum ----------------
    if (tid < 256) s_cdf[tid] = (float)__ldcg(&g_hist[tid]);  // total 2^22: exact in fp32
    __syncthreads();
    for (int off = 1; off < 256; off <<= 1) {
        float t = 0.0f;
        if (tid < 256 && tid >= off) t = s_cdf[tid - off];
        __syncthreads();
        if (tid < 256) s_cdf[tid] += t;
        __syncthreads();
    }
    float norm = s_cdf[255];
    __syncthreads();
    if (tid < 256) s_cdf[tid] = s_cdf[tid] / norm;
    __syncthreads();

    float sEq = 0.f;
    for (int i = tid; i < npairs; i += NTHR) {
        float2 v = unpackh2(s_im[i]);
        float2 r = unpackh2(s_rm[i]);
        sEq += fabsf(r.x - interp1(v.x, gmin, scale, s_cdf))
             + fabsf(r.y - interp1(v.y, gmin, scale, s_cdf));
    }
    double dEq = (double)sEq;
    for (int o = 16; o; o >>= 1) dEq += __shfl_down_sync(m, dEq, o);
    if (lane == 0) redd[0][wid] = dEq;
    __syncthreads();
    if (wid == 0) {
        dEq = redd[0][lane];
        for (int o = 16; o; o >>= 1) dEq += __shfl_down_sync(m, dEq, o);
        if (lane == 0) atomicAdd(&g_sums[3], dEq);
    }

    gridbar(3 * NCTA);

    // ---------------- Final combine ----------------
    if (cta == 0 && tid == 0) {
        double recon = __ldcg(&g_sums[0]) / (3.0 * (double)HWN);
        double denom = 2.0 * (double)(HH + 1) * (double)(WW + 2);
        double rs = __ldcg(&g_sums[1]) / (255.0 * denom);
        double is = __ldcg(&g_sums[2]) / denom;
        double eq = __ldcg(&g_sums[3]) / (double)HWN;
        out[0] = (float)(recon + 0.1 * is + 0.1 * eq + 0.01 * rs);
    }
}

extern "C" void kernel_launch(void* const* d_in, const int* in_sizes, int n_in,
                              void* d_out, int out_size) {
    const float2* in = (const float2*)d_in[0];
    const float2* Rp = (const float2*)d_in[1];
    const float2* Lp = (const float2*)d_in[2];
    (void)in_sizes; (void)n_in; (void)out_size;

    cudaFuncSetAttribute(kmain, cudaFuncAttributeMaxDynamicSharedMemorySize, SMEM_BYTES);

    k_zero<<<1, 256>>>();
    kmain<<<NCTA, NTHR, SMEM_BYTES>>>(in, Rp, Lp, (float*)d_out);
}

// round 8
// speedup vs baseline: 1.2046x; 1.2046x over previous
#include <cuda_runtime.h>
#include <cuda_fp16.h>

#define HH 2048
#define WW 2048
#define HWN (HH*WW)
#define W4 (WW/4)
#define HW4 (HWN/4)
#define NCTA 296
#define NTHR 512
#define MAXR 7
#define SUB 8

// dyn smem: s_im uint2[3584]=28672B, s_rm uint2[3584]=28672B, lut 1024B, cdf 1024B, hist 8192B
#define SMEM_BYTES (MAXR*512*8*2 + 1024 + 1024 + 256*SUB*4)

__device__ double g_sums[4];      // 0:recon 1:r_smooth(x255, int-exact) 2:ismooth 3:eq
__device__ unsigned int g_hist[256];
__device__ int g_minbits;
__device__ int g_maxbits;
__device__ unsigned int g_bar;

__global__ void k_zero() {
    int t = threadIdx.x;
    if (t < 256) g_hist[t] = 0u;
    if (t < 4) g_sums[t] = 0.0;
    if (t == 0) { g_minbits = 0x7F800000; g_maxbits = 0; g_bar = 0u; }
}

// 8-bit quantize: exact match to floorf(clip(x,0,1)*255)
__device__ __forceinline__ int q8(float x) {
    return __float2int_rd(__saturatef(x) * 255.0f);
}
// PIL 'L' grayscale, pure integer (exact: operands < 2^26)
__device__ __forceinline__ int grayi(int q0, int q1, int q2) {
    return (19595 * q0 + 38470 * q1 + 7471 * q2 + 32768) >> 16;
}

__device__ __forceinline__ unsigned packh2(float a, float b) {
    __half2 h = __floats2half2_rn(a, b);
    return *reinterpret_cast<unsigned*>(&h);
}
__device__ __forceinline__ float2 unpackh2(unsigned u) {
    __half2 h = *reinterpret_cast<__half2*>(&u);
    return __half22float2(h);
}

// Software grid barrier; residency: launch_bounds(512,2), 64 regs, 67.6KB smem
// -> exactly 2 CTAs/SM, 2*148 = 296 = NCTA (GB300: 152 SMs, headroom).
__device__ __forceinline__ void gridbar(unsigned target) {
    __syncthreads();
    if (threadIdx.x == 0) {
        __threadfence();
        atomicAdd(&g_bar, 1u);
        while (*(volatile unsigned*)&g_bar < target) { }
    }
    __syncthreads();
    __threadfence();
}

__device__ __forceinline__ float interp1(float x, float gmin, float scale, const float* cdf) {
    float u = fmaxf((x - gmin) * scale, 0.0f);   // fp16-rounded x may dip below gmin
    int k = (int)u;
    if (k >= 255) return cdf[255];
    float f = u - (float)k;
    return cdf[k] + (cdf[k + 1] - cdf[k]) * f;
}

__global__ __launch_bounds__(NTHR, 2) void kmain(const float4* __restrict__ in,
                                                 const float4* __restrict__ Rp,
                                                 const float4* __restrict__ Lp,
                                                 float* __restrict__ out) {
    extern __shared__ char sm[];
    uint2*    s_im  = (uint2*)sm;                          // fp16x4 im_max
    uint2*    s_rm  = (uint2*)(sm + MAXR*512*8);           // fp16x4 r_max
    float*    s_lut = (float*)(sm + MAXR*512*16);
    float*    s_cdf = s_lut + 256;
    unsigned* s_h   = (unsigned*)(s_cdf + 256);
    __shared__ double redd[3][16];
    __shared__ float  redf[2][16];

    const int tid = threadIdx.x;
    const int cta = blockIdx.x;

    // slab: CTAs 0..271 -> 7 rows, 272..295 -> 6 rows (272*7 + 24*6 = 2048)
    int nr, r0;
    if (cta < 272) { nr = 7; r0 = cta * 7; }
    else           { nr = 6; r0 = 1904 + (cta - 272) * 6; }

    for (int i = tid; i < 256; i += NTHR)
        s_lut[i] = __expf((float)i * (-10.0f / 255.0f));
    __syncthreads();

    // ---------------- Phase 1 ----------------
    const int col = tid;
    int gPx, gPy, gPz, gPw;
    float4 lP;
    if (r0 == 0) {
        gPx = gPy = gPz = gPw = 0;
        lP = make_float4(0.f, 0.f, 0.f, 0.f);
    } else {
        int idx = (r0 - 1) * W4 + col;
        float4 b0 = Rp[idx], b1 = Rp[idx + HW4], b2 = Rp[idx + 2 * HW4];
        gPx = grayi(q8(b0.x), q8(b1.x), q8(b2.x));
        gPy = grayi(q8(b0.y), q8(b1.y), q8(b2.y));
        gPz = grayi(q8(b0.z), q8(b1.z), q8(b2.z));
        gPw = grayi(q8(b0.w), q8(b1.w), q8(b2.w));
        lP = Lp[idx];
    }

    float sRec = 0.f, sIs = 0.f;
    int   sRsI = 0;                       // exact integer r_smooth accumulator
    float vmin = 3.0f, vmax = -1.0f;

    #pragma unroll 2
    for (int rr = 0; rr < nr; rr++) {
        int idx = (r0 + rr) * W4 + col;
        float4 a0 = in[idx], a1 = in[idx + HW4], a2 = in[idx + 2 * HW4];
        float4 b0 = Rp[idx], b1 = Rp[idx + HW4], b2 = Rp[idx + 2 * HW4];
        float4 lv = Lp[idx];

        sRec +=
            fabsf(b0.x * lv.x - a0.x) + fabsf(b0.y * lv.y - a0.y) +
            fabsf(b0.z * lv.z - a0.z) + fabsf(b0.w * lv.w - a0.w) +
            fabsf(b1.x * lv.x - a1.x) + fabsf(b1.y * lv.y - a1.y) +
            fabsf(b1.z * lv.z - a1.z) + fabsf(b1.w * lv.w - a1.w) +
            fabsf(b2.x * lv.x - a2.x) + fabsf(b2.y * lv.y - a2.y) +
            fabsf(b2.z * lv.z - a2.z) + fabsf(b2.w * lv.w - a2.w);

        float imx = fmaxf(a0.x, fmaxf(a1.x, a2.x));
        float imy = fmaxf(a0.y, fmaxf(a1.y, a2.y));
        float imz = fmaxf(a0.z, fmaxf(a1.z, a2.z));
        float imw = fmaxf(a0.w, fmaxf(a1.w, a2.w));
        float rmx = fmaxf(b0.x, fmaxf(b1.x, b2.x));
        float rmy = fmaxf(b0.y, fmaxf(b1.y, b2.y));
        float rmz = fmaxf(b0.z, fmaxf(b1.z, b2.z));
        float rmw = fmaxf(b0.w, fmaxf(b1.w, b2.w));

        int li = rr * 512 + col;
        s_im[li] = make_uint2(packh2(imx, imy), packh2(imz, imw));
        s_rm[li] = make_uint2(packh2(rmx, rmy), packh2(rmz, rmw));

        vmin = fminf(vmin, fminf(fminf(imx, imy), fminf(imz, imw)));
        vmax = fmaxf(vmax, fmaxf(fmaxf(imx, imy), fmaxf(imz, imw)));

        int gx = grayi(q8(b0.x), q8(b1.x), q8(b2.x));
        int gy = grayi(q8(b0.y), q8(b1.y), q8(b2.y));
        int gz = grayi(q8(b0.z), q8(b1.z), q8(b2.z));
        int gw = grayi(q8(b0.w), q8(b1.w), q8(b2.w));

        int dgx = abs(gx - gPx), dgy = abs(gy - gPy);
        int dgz = abs(gz - gPz), dgw = abs(gw - gPw);
        sRsI += dgx + dgy + dgz + dgw + 2 * (gx + gy + gz + gw);

        sIs += fabsf(lv.x - lP.x) * s_lut[dgx] + 2.0f * fabsf(lv.x) * s_lut[gx]
             + fabsf(lv.y - lP.y) * s_lut[dgy] + 2.0f * fabsf(lv.y) * s_lut[gy]
             + fabsf(lv.z - lP.z) * s_lut[dgz] + 2.0f * fabsf(lv.z) * s_lut[gz]
             + fabsf(lv.w - lP.w) * s_lut[dgw] + 2.0f * fabsf(lv.w) * s_lut[gw];

        gPx = gx; gPy = gy; gPz = gz; gPw = gw;
        lP = lv;
    }

    if (r0 + nr == HH) {   // bottom padded edge
        sRsI += gPx + gPy + gPz + gPw;
        sIs  += fabsf(lP.x) * s_lut[gPx] + fabsf(lP.y) * s_lut[gPy]
              + fabsf(lP.z) * s_lut[gPz] + fabsf(lP.w) * s_lut[gPw];
    }

    // block reduce (16 warps)
    double dRec = (double)sRec, dIs = (double)sIs;
    int    iRs = sRsI;
    const unsigned m = 0xffffffffu;
    for (int o = 16; o; o >>= 1) {
        dRec += __shfl_down_sync(m, dRec, o);
        dIs  += __shfl_down_sync(m, dIs,  o);
        iRs  += __shfl_down_sync(m, iRs,  o);
        vmin = fminf(vmin, __shfl_down_sync(m, vmin, o));
        vmax = fmaxf(vmax, __shfl_down_sync(m, vmax, o));
    }
    int lane = tid & 31, wid = tid >> 5;
    if (lane == 0) {
        redd[0][wid] = dRec; redd[1][wid] = (double)iRs; redd[2][wid] = dIs;
        redf[0][wid] = vmin; redf[1][wid] = vmax;
    }
    __syncthreads();
    if (wid == 0) {
        double dRs;
        dRec = (lane < 16) ? redd[0][lane] : 0.0;
        dRs  = (lane < 16) ? redd[1][lane] : 0.0;
        dIs  = (lane < 16) ? redd[2][lane] : 0.0;
        vmin = (lane < 16) ? redf[0][lane] : 3.0f;
        vmax = (lane < 16) ? redf[1][lane] : -1.0f;
        for (int o = 8; o; o >>= 1) {
            dRec += __shfl_down_sync(m, dRec, o);
            dRs  += __shfl_down_sync(m, dRs,  o);
            dIs  += __shfl_down_sync(m, dIs,  o);
            vmin = fminf(vmin, __shfl_down_sync(m, vmin, o));
            vmax = fmaxf(vmax, __shfl_down_sync(m, vmax, o));
        }
        if (lane == 0) {
            atomicAdd(&g_sums[0], dRec);
            atomicAdd(&g_sums[1], dRs);
            atomicAdd(&g_sums[2], dIs);
            atomicMin(&g_minbits, __float_as_int(vmin));
            atomicMax(&g_maxbits, __float_as_int(vmax));
        }
    }

    gridbar(NCTA);

    // ---------------- Phase 2: histogram from smem ----------------
    const float gmin = __int_as_float(__ldcg(&g_minbits));
    const float gmax = __int_as_float(__ldcg(&g_maxbits));
    const float scale = 256.0f / (gmax - gmin);

    for (int i = tid; i < 256 * SUB; i += NTHR) s_h[i] = 0u;
    __syncthreads();
    const unsigned sub = tid & (SUB - 1);
    const int nelem = nr * 512;
    for (int i = tid; i < nelem; i += NTHR) {
        uint2 u = s_im[i];
        float2 v0 = unpackh2(u.x);
        float2 v1 = unpackh2(u.y);
        int k0 = min(255, (int)fmaxf((v0.x - gmin) * scale, 0.0f));
        int k1 = min(255, (int)fmaxf((v0.y - gmin) * scale, 0.0f));
        int k2 = min(255, (int)fmaxf((v1.x - gmin) * scale, 0.0f));
        int k3 = min(255, (int)fmaxf((v1.y - gmin) * scale, 0.0f));
        atomicAdd(&s_h[k0 * SUB + sub], 1u);
        atomicAdd(&s_h[k1 * SUB + sub], 1u);
        atomicAdd(&s_h[k2 * SUB + sub], 1u);
        atomicAdd(&s_h[k3 * SUB + sub], 1u);
    }
    __syncthreads();
    if (tid < 256) {
        unsigned s = 0;
        #pragma unroll
        for (int j = 0; j < SUB; j++) s += s_h[tid * SUB + j];
        if (s) atomicAdd(&g_hist[tid], s);
    }

    gridbar(2 * NCTA);

    // ---------------- Phase 3: cdf + interp + eq-sum ----------------
    if (tid < 256) s_cdf[tid] = (float)__ldcg(&g_hist[tid]);   // total 2^22: exact
    __syncthreads();
    for (int off = 1; off < 256; off <<= 1) {
        float t = 0.0f;
        if (tid < 256 && tid >= off) t = s_cdf[tid - off];
        __syncthreads();
        if (tid < 256) s_cdf[tid] += t;
        __syncthreads();
    }
    float norm = s_cdf[255];
    __syncthreads();
    if (tid < 256) s_cdf[tid] = s_cdf[tid] / norm;
    __syncthreads();

    float sEq = 0.f;
    for (int i = tid; i < nelem; i += NTHR) {
        uint2 u = s_im[i];
        uint2 ru = s_rm[i];
        float2 v0 = unpackh2(u.x), v1 = unpackh2(u.y);
        float2 r0f = unpackh2(ru.x), r1f = unpackh2(ru.y);
        sEq += fabsf(r0f.x - interp1(v0.x, gmin, scale, s_cdf))
             + fabsf(r0f.y - interp1(v0.y, gmin, scale, s_cdf))
             + fabsf(r1f.x - interp1(v1.x, gmin, scale, s_cdf))
             + fabsf(r1f.y - interp1(v1.y, gmin, scale, s_cdf));
    }
    double dEq = (double)sEq;
    for (int o = 16; o; o >>= 1) dEq += __shfl_down_sync(m, dEq, o);
    if (lane == 0) redd[0][wid] = dEq;
    __syncthreads();
    if (wid == 0) {
        dEq = (lane < 16) ? redd[0][lane] : 0.0;
        for (int o = 8; o; o >>= 1) dEq += __shfl_down_sync(m, dEq, o);
        if (lane == 0) atomicAdd(&g_sums[3], dEq);
    }

    gridbar(3 * NCTA);

    // ---------------- Final combine ----------------
    if (cta == 0 && tid == 0) {
        double recon = __ldcg(&g_sums[0]) / (3.0 * (double)HWN);
        double denom = 2.0 * (double)(HH + 1) * (double)(WW + 2);
        double rs = __ldcg(&g_sums[1]) / (255.0 * denom);
        double is = __ldcg(&g_sums[2]) / denom;
        double eq = __ldcg(&g_sums[3]) / (double)HWN;
        out[0] = (float)(recon + 0.1 * is + 0.1 * eq + 0.01 * rs);
    }
}

extern "C" void kernel_launch(void* const* d_in, const int* in_sizes, int n_in,
                              void* d_out, int out_size) {
    const float4* in = (const float4*)d_in[0];
    const float4* Rp = (const float4*)d_in[1];
    const float4* Lp = (const float4*)d_in[2];
    (void)in_sizes; (void)n_in; (void)out_size;

    cudaFuncSetAttribute(kmain, cudaFuncAttributeMaxDynamicSharedMemorySize, SMEM_BYTES);

    k_zero<<<1, 256>>>();
    kmain<<<NCTA, NTHR, SMEM_BYTES>>>(in, Rp, Lp, (float*)d_out);
}

// round 9
// speedup vs baseline: 1.2601x; 1.0460x over previous
#include <cuda_runtime.h>
#include <cuda_fp16.h>

#define HH 2048
#define WW 2048
#define HWN (HH*WW)
#define W4 (WW/4)
#define HW4 (HWN/4)
#define NCTA 148
#define NTHR 512
#define MAXR 14
#define SUB 8

// dyn smem: s_im uint2[7168]=57344B, s_rm uint2[7168]=57344B, lut 1KB, cdf 1KB, hist/cdfp 8KB
#define SMEM_BYTES (MAXR*512*8*2 + 1024 + 1024 + 256*SUB*4)

__device__ double g_sums[4];      // 0:recon 1:r_smooth(x255, int-exact) 2:ismooth 3:eq
__device__ unsigned int g_hist[256];
__device__ int g_minbits;
__device__ int g_maxbits;
__device__ unsigned int g_bar;

__global__ void k_zero() {
    int t = threadIdx.x;
    if (t < 256) g_hist[t] = 0u;
    if (t < 4) g_sums[t] = 0.0;
    if (t == 0) { g_minbits = 0x7F800000; g_maxbits = 0; g_bar = 0u; }
}

__device__ __forceinline__ int q8(float x) {
    return __float2int_rd(__saturatef(x) * 255.0f);
}
__device__ __forceinline__ int grayi(int q0, int q1, int q2) {
    return (19595 * q0 + 38470 * q1 + 7471 * q2 + 32768) >> 16;
}
__device__ __forceinline__ unsigned packh2(float a, float b) {
    __half2 h = __floats2half2_rn(a, b);
    return *reinterpret_cast<unsigned*>(&h);
}
__device__ __forceinline__ float2 unpackh2(unsigned u) {
    __half2 h = *reinterpret_cast<__half2*>(&u);
    return __half22float2(h);
}

// Grid barrier; residency: 1 CTA/SM (125KB smem), NCTA=148 <= SM count.
__device__ __forceinline__ void gridbar(unsigned target) {
    __syncthreads();
    if (threadIdx.x == 0) {
        __threadfence();
        atomicAdd(&g_bar, 1u);
        while (*(volatile unsigned*)&g_bar < target) { }
    }
    __syncthreads();
    __threadfence();
}

// interp with paired cdf: p[k] = (cdf[k], cdf[k+1]); p[255] = (cdf255, cdf255)
__device__ __forceinline__ float interp1p(float x, float gmin, float scale, const float2* cdfp) {
    float u = fmaxf((x - gmin) * scale, 0.0f);
    int k = min((int)u, 255);
    float2 p = cdfp[k];
    return fmaf(p.y - p.x, u - (float)k, p.x);   // slope 0 at k=255 -> returns cdf[255]
}

__global__ __launch_bounds__(NTHR, 1) void kmain(const float4* __restrict__ in,
                                                 const float4* __restrict__ Rp,
                                                 const float4* __restrict__ Lp,
                                                 float* __restrict__ out) {
    extern __shared__ char sm[];
    uint2*    s_im  = (uint2*)sm;                          // fp16x4 im_max
    uint2*    s_rm  = (uint2*)(sm + MAXR*512*8);           // fp16x4 r_max
    float*    s_lut = (float*)(sm + MAXR*512*16);
    float*    s_cdf = s_lut + 256;
    unsigned* s_h   = (unsigned*)(s_cdf + 256);            // phase 2; reused as cdfp in phase 3
    float2*   s_cdfp = (float2*)s_h;
    __shared__ double redd[3][16];
    __shared__ float  redf[2][16];

    const int tid = threadIdx.x;
    const int cta = blockIdx.x;

    // slab: CTAs 0..123 -> 14 rows, 124..147 -> 13 rows (124*14 + 24*13 = 2048)
    int nr, r0;
    if (cta < 124) { nr = 14; r0 = cta * 14; }
    else           { nr = 13; r0 = 1736 + (cta - 124) * 13; }

    for (int i = tid; i < 256; i += NTHR)
        s_lut[i] = __expf((float)i * (-10.0f / 255.0f));
    __syncthreads();

    // ---------------- Phase 1: software-pipelined streaming pass ----------------
    const int col = tid;
    int gPx, gPy, gPz, gPw;
    float4 lP;
    if (r0 == 0) {
        gPx = gPy = gPz = gPw = 0;
        lP = make_float4(0.f, 0.f, 0.f, 0.f);
    } else {
        int idx = (r0 - 1) * W4 + col;
        float4 b0 = __ldcs(&Rp[idx]), b1 = __ldcs(&Rp[idx + HW4]), b2 = __ldcs(&Rp[idx + 2 * HW4]);
        gPx = grayi(q8(b0.x), q8(b1.x), q8(b2.x));
        gPy = grayi(q8(b0.y), q8(b1.y), q8(b2.y));
        gPz = grayi(q8(b0.z), q8(b1.z), q8(b2.z));
        gPw = grayi(q8(b0.w), q8(b1.w), q8(b2.w));
        lP = __ldcs(&Lp[idx]);
    }

    float sRec = 0.f, sIs = 0.f;
    int   sRsI = 0;
    float vmin = 3.0f, vmax = -1.0f;

    int idx = r0 * W4 + col;
    float4 a0 = __ldcs(&in[idx]), a1 = __ldcs(&in[idx + HW4]), a2 = __ldcs(&in[idx + 2 * HW4]);
    float4 b0 = __ldcs(&Rp[idx]), b1 = __ldcs(&Rp[idx + HW4]), b2 = __ldcs(&Rp[idx + 2 * HW4]);
    float4 lv = __ldcs(&Lp[idx]);

    auto body = [&](int rr) {
        sRec +=
            fabsf(b0.x * lv.x - a0.x) + fabsf(b0.y * lv.y - a0.y) +
            fabsf(b0.z * lv.z - a0.z) + fabsf(b0.w * lv.w - a0.w) +
            fabsf(b1.x * lv.x - a1.x) + fabsf(b1.y * lv.y - a1.y) +
            fabsf(b1.z * lv.z - a1.z) + fabsf(b1.w * lv.w - a1.w) +
            fabsf(b2.x * lv.x - a2.x) + fabsf(b2.y * lv.y - a2.y) +
            fabsf(b2.z * lv.z - a2.z) + fabsf(b2.w * lv.w - a2.w);

        float imx = fmaxf(a0.x, fmaxf(a1.x, a2.x));
        float imy = fmaxf(a0.y, fmaxf(a1.y, a2.y));
        float imz = fmaxf(a0.z, fmaxf(a1.z, a2.z));
        float imw = fmaxf(a0.w, fmaxf(a1.w, a2.w));
        float rmx = fmaxf(b0.x, fmaxf(b1.x, b2.x));
        float rmy = fmaxf(b0.y, fmaxf(b1.y, b2.y));
        float rmz = fmaxf(b0.z, fmaxf(b1.z, b2.z));
        float rmw = fmaxf(b0.w, fmaxf(b1.w, b2.w));

        int li = rr * 512 + col;
        s_im[li] = make_uint2(packh2(imx, imy), packh2(imz, imw));
        s_rm[li] = make_uint2(packh2(rmx, rmy), packh2(rmz, rmw));

        vmin = fminf(vmin, fminf(fminf(imx, imy), fminf(imz, imw)));
        vmax = fmaxf(vmax, fmaxf(fmaxf(imx, imy), fmaxf(imz, imw)));

        int gx = grayi(q8(b0.x), q8(b1.x), q8(b2.x));
        int gy = grayi(q8(b0.y), q8(b1.y), q8(b2.y));
        int gz = grayi(q8(b0.z), q8(b1.z), q8(b2.z));
        int gw = grayi(q8(b0.w), q8(b1.w), q8(b2.w));

        int dgx = abs(gx - gPx), dgy = abs(gy - gPy);
        int dgz = abs(gz - gPz), dgw = abs(gw - gPw);
        sRsI += dgx + dgy + dgz + dgw + 2 * (gx + gy + gz + gw);

        sIs += fabsf(lv.x - lP.x) * s_lut[dgx] + 2.0f * fabsf(lv.x) * s_lut[gx]
             + fabsf(lv.y - lP.y) * s_lut[dgy] + 2.0f * fabsf(lv.y) * s_lut[gy]
             + fabsf(lv.z - lP.z) * s_lut[dgz] + 2.0f * fabsf(lv.z) * s_lut[gz]
             + fabsf(lv.w - lP.w) * s_lut[dgw] + 2.0f * fabsf(lv.w) * s_lut[gw];

        gPx = gx; gPy = gy; gPz = gz; gPw = gw;
        lP = lv;
    };

    #pragma unroll 1
    for (int rr = 0; rr < nr - 1; rr++) {
        int nidx = idx + W4;
        float4 na0 = __ldcs(&in[nidx]), na1 = __ldcs(&in[nidx + HW4]), na2 = __ldcs(&in[nidx + 2 * HW4]);
        float4 nb0 = __ldcs(&Rp[nidx]), nb1 = __ldcs(&Rp[nidx + HW4]), nb2 = __ldcs(&Rp[nidx + 2 * HW4]);
        float4 nlv = __ldcs(&Lp[nidx]);
        body(rr);
        a0 = na0; a1 = na1; a2 = na2;
        b0 = nb0; b1 = nb1; b2 = nb2;
        lv = nlv;
        idx = nidx;
    }
    body(nr - 1);

    if (r0 + nr == HH) {   // bottom padded edge
        sRsI += gPx + gPy + gPz + gPw;
        sIs  += fabsf(lP.x) * s_lut[gPx] + fabsf(lP.y) * s_lut[gPy]
              + fabsf(lP.z) * s_lut[gPz] + fabsf(lP.w) * s_lut[gPw];
    }

    // block reduce (16 warps)
    double dRec = (double)sRec, dIs = (double)sIs;
    int    iRs = sRsI;
    const unsigned m = 0xffffffffu;
    for (int o = 16; o; o >>= 1) {
        dRec += __shfl_down_sync(m, dRec, o);
        dIs  += __shfl_down_sync(m, dIs,  o);
        iRs  += __shfl_down_sync(m, iRs,  o);
        vmin = fminf(vmin, __shfl_down_sync(m, vmin, o));
        vmax = fmaxf(vmax, __shfl_down_sync(m, vmax, o));
    }
    int lane = tid & 31, wid = tid >> 5;
    if (lane == 0) {
        redd[0][wid] = dRec; redd[1][wid] = (double)iRs; redd[2][wid] = dIs;
        redf[0][wid] = vmin; redf[1][wid] = vmax;
    }
    __syncthreads();
    if (wid == 0) {
        double dRs;
        dRec = (lane < 16) ? redd[0][lane] : 0.0;
        dRs  = (lane < 16) ? redd[1][lane] : 0.0;
        dIs  = (lane < 16) ? redd[2][lane] : 0.0;
        vmin = (lane < 16) ? redf[0][lane] : 3.0f;
        vmax = (lane < 16) ? redf[1][lane] : -1.0f;
        for (int o = 8; o; o >>= 1) {
            dRec += __shfl_down_sync(m, dRec, o);
            dRs  += __shfl_down_sync(m, dRs,  o);
            dIs  += __shfl_down_sync(m, dIs,  o);
            vmin = fminf(vmin, __shfl_down_sync(m, vmin, o));
            vmax = fmaxf(vmax, __shfl_down_sync(m, vmax, o));
        }
        if (lane == 0) {
            atomicAdd(&g_sums[0], dRec);
            atomicAdd(&g_sums[1], dRs);
            atomicAdd(&g_sums[2], dIs);
            atomicMin(&g_minbits, __float_as_int(vmin));
            atomicMax(&g_maxbits, __float_as_int(vmax));
        }
    }

    gridbar(NCTA);

    // ---------------- Phase 2: histogram from smem ----------------
    const float gmin = __int_as_float(__ldcg(&g_minbits));
    const float gmax = __int_as_float(__ldcg(&g_maxbits));
    const float scale = 256.0f / (gmax - gmin);

    for (int i = tid; i < 256 * SUB; i += NTHR) s_h[i] = 0u;
    __syncthreads();
    const unsigned sub = tid & (SUB - 1);
    const int nelem = nr * 512;
    for (int i = tid; i < nelem; i += NTHR) {
        uint2 u = s_im[i];
        float2 v0 = unpackh2(u.x);
        float2 v1 = unpackh2(u.y);
        int k0 = min(255, (int)fmaxf((v0.x - gmin) * scale, 0.0f));
        int k1 = min(255, (int)fmaxf((v0.y - gmin) * scale, 0.0f));
        int k2 = min(255, (int)fmaxf((v1.x - gmin) * scale, 0.0f));
        int k3 = min(255, (int)fmaxf((v1.y - gmin) * scale, 0.0f));
        atomicAdd(&s_h[k0 * SUB + sub], 1u);
        atomicAdd(&s_h[k1 * SUB + sub], 1u);
        atomicAdd(&s_h[k2 * SUB + sub], 1u);
        atomicAdd(&s_h[k3 * SUB + sub], 1u);
    }
    __syncthreads();
    if (tid < 256) {
        unsigned s = 0;
        #pragma unroll
        for (int j = 0; j < SUB; j++) s += s_h[tid * SUB + j];
        if (s) atomicAdd(&g_hist[tid], s);
    }

    gridbar(2 * NCTA);

    // ---------------- Phase 3: cdf + paired interp + eq-sum ----------------
    if (tid < 256) s_cdf[tid] = (float)__ldcg(&g_hist[tid]);   // total 2^22: exact in fp32
    __syncthreads();
    for (int off = 1; off < 256; off <<= 1) {
        float t = 0.0f;
        if (tid < 256 && tid >= off) t = s_cdf[tid - off];
        __syncthreads();
        if (tid < 256) s_cdf[tid] += t;
        __syncthreads();
    }
    float norm = s_cdf[255];
    __syncthreads();
    if (tid < 256) s_cdf[tid] = s_cdf[tid] / norm;
    __syncthreads();
    if (tid < 256) {   // build pairs over the (now finished) hist region
        float c0 = s_cdf[tid];
        float c1 = (tid < 255) ? s_cdf[tid + 1] : c0;
        s_cdfp[tid] = make_float2(c0, c1);
    }
    __syncthreads();

    float sEq = 0.f;
    for (int i = tid; i < nelem; i += NTHR) {
        uint2 u = s_im[i];
        uint2 ru = s_rm[i];
        float2 v0 = unpackh2(u.x), v1 = unpackh2(u.y);
        float2 r0f = unpackh2(ru.x), r1f = unpackh2(ru.y);
        sEq += fabsf(r0f.x - interp1p(v0.x, gmin, scale, s_cdfp))
             + fabsf(r0f.y - interp1p(v0.y, gmin, scale, s_cdfp))
             + fabsf(r1f.x - interp1p(v1.x, gmin, scale, s_cdfp))
             + fabsf(r1f.y - interp1p(v1.y, gmin, scale, s_cdfp));
    }
    double dEq = (double)sEq;
    for (int o = 16; o; o >>= 1) dEq += __shfl_down_sync(m, dEq, o);
    if (lane == 0) redd[0][wid] = dEq;
    __syncthreads();
    if (wid == 0) {
        dEq = (lane < 16) ? redd[0][lane] : 0.0;
        for (int o = 8; o; o >>= 1) dEq += __shfl_down_sync(m, dEq, o);
        if (lane == 0) atomicAdd(&g_sums[3], dEq);
    }

    gridbar(3 * NCTA);

    // ---------------- Final combine ----------------
    if (cta == 0 && tid == 0) {
        double recon = __ldcg(&g_sums[0]) / (3.0 * (double)HWN);
        double denom = 2.0 * (double)(HH + 1) * (double)(WW + 2);
        double rs = __ldcg(&g_sums[1]) / (255.0 * denom);
        double is = __ldcg(&g_sums[2]) / denom;
        double eq = __ldcg(&g_sums[3]) / (double)HWN;
        out[0] = (float)(recon + 0.1 * is + 0.1 * eq + 0.01 * rs);
    }
}

extern "C" void kernel_launch(void* const* d_in, const int* in_sizes, int n_in,
                              void* d_out, int out_size) {
    const float4* in = (const float4*)d_in[0];
    const float4* Rp = (const float4*)d_in[1];
    const float4* Lp = (const float4*)d_in[2];
    (void)in_sizes; (void)n_in; (void)out_size;

    cudaFuncSetAttribute(kmain, cudaFuncAttributeMaxDynamicSharedMemorySize, SMEM_BYTES);

    k_zero<<<1, 256>>>();
    kmain<<<NCTA, NTHR, SMEM_BYTES>>>(in, Rp, Lp, (float*)d_out);
}